// round 9
// baseline (speedup 1.0000x reference)
#include <cuda_runtime.h>
#include <cuda_bf16.h>
#include <math.h>

// SpikeToCalciumDoubleExp: out[b,t] = sum_{j=0}^{K-1} kernel[j] * u[b, t+K-1-j]
// kernel[j] = (g1^{j+1} - g2^{j+1})/scale, g = exp(-1/tau), tau1=20, tau2=2, K=121.
//
// Per-channel state P(j) = (g/scale) * sum_{r=0}^{120} g^{120-r} u[j+r]; exact
// recursion P(j+1) = g*P(j) + (g/scale)*u[j+121] - (g^{122}/scale)*u[j].
//
// Seed decomposition (121 = 3*31 + 28): each thread computes, over its own
// 31-sample chunk held in registers x[]:
//   M   = 31-tap g1 Horner,  M28 = its state after 28 taps (free snapshot),
//   H28 = 28-tap g2 Horner over x[0..27],
// and publishes all three. Thread i's seeds are then pure table lookups:
//   U1 = g1^90*M_i + g1^59*M_{i+1} + g1^28*M_{i+2} + M28_{i+3}
//   Q  = (g2/scale) * H28_{i+3}      (g2 support truncated to last 28 taps,
//                                     dropped weight <= 1.7e-6; g2^122 ~ 0)
// Recursion reuses x[] for the old-sample term (no LDS) and writes outputs
// back into x[] slots. Stride-31 (odd) smem access: bank-conflict-free.

#define THREADS 256
#define LPT 31                       // outputs per thread
#define CHUNK (THREADS * LPT)        // 7936 outputs per block
#define WIN (CHUNK + 128)            // input window incl. K-1 lookahead
#define NM (THREADS + 3)             // Horner tables incl. 3 overhang chunks

template<int KC>   // KC>0: compile-time K=121 fast path; KC==0: runtime-K fallback
__global__ void __launch_bounds__(THREADS, 5)
spike2calcium_kernel(const float* __restrict__ u, float* __restrict__ out,
                     int Krt, int T_out, int in_w) {
    __shared__ float sm[WIN];
    __shared__ float Msm[NM];
    __shared__ float M28sm[NM];
    __shared__ float H28sm[NM];

    const int K   = (KC > 0) ? KC : Krt;
    const int tid = threadIdx.x;
    const int b   = blockIdx.y;
    const int t0  = blockIdx.x * CHUNK;

    // ---- filter constants ----
    const float tau1 = 20.0f;   // TAU1 * HZ
    const float tau2 = 2.0f;    // TAU2 * HZ
    const float rr = tau1 / tau2;
    const float dd = tau1 - tau2;
    const float scale = powf(rr, -tau2 / dd) - powf(rr, -tau1 / dd);
    const float inv_scale = 1.0f / scale;
    const float g1 = expf(-1.0f / tau1);
    const float g2 = expf(-1.0f / tau2);
    const float cn1 = g1 * inv_scale;
    const float cn2 = g2 * inv_scale;

    // ---- phase 1: cooperative window load (float4, coalesced, conflict-free) ----
    const float* row = u + (size_t)b * in_w + t0;
    const int wlen = min(WIN, in_w - t0);
    const int nv = wlen >> 2;
    const float4* row4 = (const float4*)row;
    for (int v = tid; v < nv; v += THREADS)
        *(float4*)&sm[v << 2] = row4[v];
    for (int j = (nv << 2) + tid; j < wlen; j += THREADS)
        sm[j] = row[j];
    __syncthreads();

    const int base = tid * LPT;
    int nout = T_out - t0 - base;
    nout = min(nout, LPT);

    if (KC > 0) {
        // ---- phase 2: own-chunk Horners over register array x[] ----
        float x[LPT];
        float M = 0.0f, H2 = 0.0f, M28 = 0.0f;
        #pragma unroll
        for (int r = 0; r < LPT; ++r) {
            x[r] = sm[base + r];
            M = fmaf(M, g1, x[r]);
            if (r < 28) H2 = fmaf(H2, g2, x[r]);
            if (r == 27) M28 = M;
        }
        Msm[tid]   = M;
        M28sm[tid] = M28;
        H28sm[tid] = H2;
        if (tid < 3) {                      // overhang chunks 256..258
            float Mo = 0.0f, H2o = 0.0f, M28o = 0.0f;
            const int ob = CHUNK + tid * LPT;
            #pragma unroll
            for (int r = 0; r < LPT; ++r) {
                float v = sm[ob + r];
                Mo = fmaf(Mo, g1, v);
                if (r < 28) H2o = fmaf(H2o, g2, v);
                if (r == 27) M28o = Mo;
            }
            Msm[THREADS + tid]   = Mo;
            M28sm[THREADS + tid] = M28o;
            H28sm[THREADS + tid] = H2o;
        }
        __syncthreads();                    // tables ready

        float o0 = 0.0f;
        if (nout > 0) {
            const float c90 = expf(-90.0f / tau1);   // g1^90
            const float c59 = expf(-59.0f / tau1);   // g1^59
            const float c28 = expf(-28.0f / tau1);   // g1^28
            float U1 = fmaf(c90, M,
                       fmaf(c59, Msm[tid + 1],
                       fmaf(c28, Msm[tid + 2], M28sm[tid + 3])));
            float P = cn1 * U1;
            float Q = cn2 * H28sm[tid + 3];
            o0 = P - Q;

            const float co1 = expf(-(float)(KC + 1) / tau1) * inv_scale;  // g1^122/scale
            #pragma unroll
            for (int t = 1; t < LPT; ++t) {
                float xn = sm[base + t + KC - 1];
                float xo = x[t - 1];           // register, no LDS
                P = fmaf(g1, P, fmaf(cn1, xn, -co1 * xo));
                Q = fmaf(g2, Q, cn2 * xn);     // g2^122/scale ~ 3e-27: dropped
                x[t - 1] = P - Q;              // o[t] reuses x[t-1]'s slot
            }
        }

        // ---- restage outputs through smem for coalesced float4 stores ----
        __syncthreads();                    // everyone done reading input window
        if (nout > 0) {
            sm[base] = o0;
            #pragma unroll
            for (int t = 1; t < LPT; ++t)
                if (t < nout) sm[base + t] = x[t - 1];
        }
        __syncthreads();
    } else {
        // runtime-K fallback: direct full Horner seed + recursion
        float o[LPT];
        if (nout > 0) {
            float H1 = 0.0f, H2 = 0.0f;
            for (int r = 0; r < K; ++r) {
                float v = sm[base + r];
                H1 = fmaf(H1, g1, v);
                H2 = fmaf(H2, g2, v);
            }
            float P = H1 * cn1;
            float Q = H2 * cn2;
            o[0] = P - Q;
            const float co1 = expf(-(float)(K + 1) / tau1) * inv_scale;
            const float co2 = expf(-(float)(K + 1) / tau2) * inv_scale;
            #pragma unroll 8
            for (int t = 1; t < LPT; ++t) {
                float xn = sm[base + t + K - 1];
                float xo = sm[base + t - 1];
                P = fmaf(g1, P, fmaf(cn1, xn, -co1 * xo));
                Q = fmaf(g2, Q, fmaf(cn2, xn, -co2 * xo));
                o[t] = P - Q;
            }
        }
        __syncthreads();
        if (nout > 0) {
            #pragma unroll
            for (int t = 0; t < LPT; ++t)
                if (t < nout) sm[base + t] = o[t];
        }
        __syncthreads();
    }

    const int olen = min(CHUNK, T_out - t0);
    float* orow = out + (size_t)b * T_out + t0;
    const int nov = olen >> 2;
    for (int v = tid; v < nov; v += THREADS)
        *(float4*)(orow + (v << 2)) = *(const float4*)&sm[v << 2];
    for (int j = (nov << 2) + tid; j < olen; j += THREADS)
        orow[j] = sm[j];
}

extern "C" void kernel_launch(void* const* d_in, const int* in_sizes, int n_in,
                              void* d_out, int out_size) {
    const float* u = (const float*)d_in[0];
    const int K = in_sizes[1];                              // 121
    const int rows  = (in_sizes[0] - out_size) / (K - 1);   // 1024
    const int T_out = out_size / rows;                      // 30000
    const int in_w  = T_out + K - 1;                        // 30120

    const int n_chunks = (T_out + CHUNK - 1) / CHUNK;       // 4
    dim3 grid(n_chunks, rows);
    if (K == 121)
        spike2calcium_kernel<121><<<grid, THREADS>>>(u, (float*)d_out, K, T_out, in_w);
    else
        spike2calcium_kernel<0><<<grid, THREADS>>>(u, (float*)d_out, K, T_out, in_w);
}

// round 10
// speedup vs baseline: 1.0791x; 1.0791x over previous
#include <cuda_runtime.h>
#include <cuda_bf16.h>
#include <math.h>
#include <stdint.h>

// SpikeToCalciumDoubleExp: out[b,t] = sum_{j=0}^{K-1} kernel[j] * u[b, t+K-1-j]
// kernel[j] = (g1^{j+1} - g2^{j+1})/scale, g = exp(-1/tau), tau1=20, tau2=2, K=121.
//
// Exact per-channel recursion P(j+1) = g*P(j) + (g/scale)*u[j+121]
//                                    - (g^{122}/scale)*u[j].
// Seed decomposition (121 = 3*31 + 28), published-Horner tables as in R8/R9:
//   M (31-tap g1 Horner), M28 (28-tap snapshot), H28 (28-tap g2 Horner);
//   U1 = g1^90*M_i + g1^59*M_{i+1} + g1^28*M_{i+2} + M28_{i+3};
//   Q  = (g2/scale)*H28_{i+3}   (g2 support = last 28 taps; drop <= 1.7e-6).
//
// NEW (this round): 2 chunks per block, double-buffered via cp.async.
// Both chunk windows are issued as fire-and-forget cp.async groups before any
// compute, so chunk 1's HBM traffic overlaps chunk 0's compute+store phases.
// This breaks the load/compute/store phase alternation that capped every pipe
// near 50%.

#define THREADS 256
#define LPT 31                       // outputs per thread
#define CHUNK (THREADS * LPT)        // 7936 outputs per chunk
#define WIN (CHUNK + 128)            // input window incl. K-1 lookahead
#define NM (THREADS + 3)             // Horner tables incl. 3 overhang chunks
#define NCPB 2                       // chunks per block (double buffer)

__device__ __forceinline__ void cp_async16(uint32_t saddr, const float* gptr) {
    asm volatile("cp.async.cg.shared.global [%0], [%1], 16;\n"
                 :: "r"(saddr), "l"(gptr));
}
__device__ __forceinline__ void cp_commit() {
    asm volatile("cp.async.commit_group;\n");
}
template<int N> __device__ __forceinline__ void cp_wait() {
    asm volatile("cp.async.wait_group %0;\n" :: "n"(N));
}

// ---------------- pipelined K=121 fast path ----------------
__global__ void __launch_bounds__(THREADS, 3)
spike2calcium_pipe(const float* __restrict__ u, float* __restrict__ out,
                   int T_out, int in_w) {
    extern __shared__ float dynsm[];          // NCPB buffers of WIN floats
    __shared__ float Msm[NM], M28sm[NM], H28sm[NM];

    const int tid = threadIdx.x;
    const int b   = blockIdx.y;
    const int c0  = blockIdx.x * NCPB;        // first global chunk index

    // ---- filter constants ----
    const float tau1 = 20.0f, tau2 = 2.0f;
    const float rr = tau1 / tau2, dd = tau1 - tau2;
    const float scale = powf(rr, -tau2 / dd) - powf(rr, -tau1 / dd);
    const float inv_scale = 1.0f / scale;
    const float g1 = expf(-1.0f / tau1);
    const float g2 = expf(-1.0f / tau2);
    const float cn1 = g1 * inv_scale;
    const float cn2 = g2 * inv_scale;
    const float co1 = expf(-122.0f / tau1) * inv_scale;   // g1^122/scale
    const float c90 = expf(-90.0f / tau1);
    const float c59 = expf(-59.0f / tau1);
    const float c28 = expf(-28.0f / tau1);

    const float* rowbase = u + (size_t)b * in_w;

    // ---- issue BOTH chunk loads up-front (fire-and-forget) ----
    #pragma unroll
    for (int c = 0; c < NCPB; ++c) {
        const int t0 = (c0 + c) * CHUNK;
        if (t0 < T_out) {
            float* buf = dynsm + c * WIN;
            const int wlen = min(WIN, in_w - t0);
            const float* gp = rowbase + t0;
            if (((uintptr_t)gp & 15u) == 0) {
                const int nv = wlen >> 2;
                uint32_t sb = (uint32_t)__cvta_generic_to_shared(buf);
                for (int v = tid; v < nv; v += THREADS)
                    cp_async16(sb + (v << 4), gp + (v << 2));
                for (int j = (nv << 2) + tid; j < wlen; j += THREADS)
                    buf[j] = gp[j];           // scalar tail (none in practice)
            } else {
                for (int j = tid; j < wlen; j += THREADS)
                    buf[j] = gp[j];
            }
        }
        cp_commit();                           // keep group count fixed
    }

    // ---- process chunks ----
    #pragma unroll
    for (int c = 0; c < NCPB; ++c) {
        const int t0 = (c0 + c) * CHUNK;
        if (t0 >= T_out) break;                // uniform across block
        float* sm = dynsm + c * WIN;

        if (c == 0) cp_wait<NCPB - 1>(); else cp_wait<0>();
        __syncthreads();                       // window c resident

        const int base = tid * LPT;
        int nout = T_out - t0 - base;
        nout = min(nout, LPT);

        // phase 2: own-chunk Horners over register array x[]
        float x[LPT];
        float M = 0.0f, H2 = 0.0f, M28 = 0.0f;
        #pragma unroll
        for (int r = 0; r < LPT; ++r) {
            x[r] = sm[base + r];
            M = fmaf(M, g1, x[r]);
            if (r < 28) H2 = fmaf(H2, g2, x[r]);
            if (r == 27) M28 = M;
        }
        Msm[tid]   = M;
        M28sm[tid] = M28;
        H28sm[tid] = H2;
        if (tid < 3) {                         // overhang chunks 256..258
            float Mo = 0.0f, H2o = 0.0f, M28o = 0.0f;
            const int ob = CHUNK + tid * LPT;
            #pragma unroll
            for (int r = 0; r < LPT; ++r) {
                float v = sm[ob + r];
                Mo = fmaf(Mo, g1, v);
                if (r < 28) H2o = fmaf(H2o, g2, v);
                if (r == 27) M28o = Mo;
            }
            Msm[THREADS + tid]   = Mo;
            M28sm[THREADS + tid] = M28o;
            H28sm[THREADS + tid] = H2o;
        }
        __syncthreads();                       // tables ready

        float o0 = 0.0f;
        if (nout > 0) {
            float U1 = fmaf(c90, M,
                       fmaf(c59, Msm[tid + 1],
                       fmaf(c28, Msm[tid + 2], M28sm[tid + 3])));
            float P = cn1 * U1;
            float Q = cn2 * H28sm[tid + 3];
            o0 = P - Q;
            #pragma unroll
            for (int t = 1; t < LPT; ++t) {
                float xn = sm[base + t + 120];
                float xo = x[t - 1];           // register, no LDS
                P = fmaf(g1, P, fmaf(cn1, xn, -co1 * xo));
                Q = fmaf(g2, Q, cn2 * xn);     // g2^122/scale ~ 3e-27: dropped
                x[t - 1] = P - Q;              // o[t] reuses x[t-1]'s slot
            }
        }

        __syncthreads();                       // all reads of window c done
        if (nout > 0) {                        // restage outputs into buffer c
            sm[base] = o0;
            #pragma unroll
            for (int t = 1; t < LPT; ++t)
                if (t < nout) sm[base + t] = x[t - 1];
        }
        __syncthreads();

        const int olen = min(CHUNK, T_out - t0);
        float* orow = out + (size_t)b * T_out + t0;
        const int nov = olen >> 2;
        for (int v = tid; v < nov; v += THREADS)
            *(float4*)(orow + (v << 2)) = *(const float4*)&sm[v << 2];
        for (int j = (nov << 2) + tid; j < olen; j += THREADS)
            orow[j] = sm[j];
        // no barrier needed: next chunk uses the other buffer; table WAR is
        // fenced by this chunk's pre-restage barrier.
    }
}

// ---------------- generic runtime-K fallback (unchanged from R9) ----------------
__global__ void __launch_bounds__(THREADS, 5)
spike2calcium_generic(const float* __restrict__ u, float* __restrict__ out,
                      int K, int T_out, int in_w) {
    __shared__ float sm[WIN];
    const int tid = threadIdx.x;
    const int b   = blockIdx.y;
    const int t0  = blockIdx.x * CHUNK;

    const float tau1 = 20.0f, tau2 = 2.0f;
    const float rr = tau1 / tau2, dd = tau1 - tau2;
    const float scale = powf(rr, -tau2 / dd) - powf(rr, -tau1 / dd);
    const float inv_scale = 1.0f / scale;
    const float g1 = expf(-1.0f / tau1);
    const float g2 = expf(-1.0f / tau2);
    const float cn1 = g1 * inv_scale;
    const float cn2 = g2 * inv_scale;

    const float* row = u + (size_t)b * in_w + t0;
    const int wlen = min(WIN, in_w - t0);
    const int nv = wlen >> 2;
    const float4* row4 = (const float4*)row;
    for (int v = tid; v < nv; v += THREADS)
        *(float4*)&sm[v << 2] = row4[v];
    for (int j = (nv << 2) + tid; j < wlen; j += THREADS)
        sm[j] = row[j];
    __syncthreads();

    const int base = tid * LPT;
    int nout = T_out - t0 - base;
    nout = min(nout, LPT);

    float o[LPT];
    if (nout > 0) {
        float H1 = 0.0f, H2 = 0.0f;
        for (int r = 0; r < K; ++r) {
            float v = sm[base + r];
            H1 = fmaf(H1, g1, v);
            H2 = fmaf(H2, g2, v);
        }
        float P = H1 * cn1;
        float Q = H2 * cn2;
        o[0] = P - Q;
        const float co1 = expf(-(float)(K + 1) / tau1) * inv_scale;
        const float co2 = expf(-(float)(K + 1) / tau2) * inv_scale;
        #pragma unroll 8
        for (int t = 1; t < LPT; ++t) {
            float xn = sm[base + t + K - 1];
            float xo = sm[base + t - 1];
            P = fmaf(g1, P, fmaf(cn1, xn, -co1 * xo));
            Q = fmaf(g2, Q, fmaf(cn2, xn, -co2 * xo));
            o[t] = P - Q;
        }
    }
    __syncthreads();
    if (nout > 0) {
        #pragma unroll
        for (int t = 0; t < LPT; ++t)
            if (t < nout) sm[base + t] = o[t];
    }
    __syncthreads();

    const int olen = min(CHUNK, T_out - t0);
    float* orow = out + (size_t)b * T_out + t0;
    const int nov = olen >> 2;
    for (int v = tid; v < nov; v += THREADS)
        *(float4*)(orow + (v << 2)) = *(const float4*)&sm[v << 2];
    for (int j = (nov << 2) + tid; j < olen; j += THREADS)
        orow[j] = sm[j];
}

extern "C" void kernel_launch(void* const* d_in, const int* in_sizes, int n_in,
                              void* d_out, int out_size) {
    const float* u = (const float*)d_in[0];
    const int K = in_sizes[1];                              // 121
    const int rows  = (in_sizes[0] - out_size) / (K - 1);   // 1024
    const int T_out = out_size / rows;                      // 30000
    const int in_w  = T_out + K - 1;                        // 30120

    if (K == 121) {
        const int n_chunks = (T_out + CHUNK - 1) / CHUNK;   // 4
        const int bx = (n_chunks + NCPB - 1) / NCPB;        // 2
        const int dsmem = NCPB * WIN * (int)sizeof(float);  // 64512 B
        cudaFuncSetAttribute(spike2calcium_pipe,
                             cudaFuncAttributeMaxDynamicSharedMemorySize, dsmem);
        dim3 grid(bx, rows);
        spike2calcium_pipe<<<grid, THREADS, dsmem>>>(u, (float*)d_out, T_out, in_w);
    } else {
        const int n_chunks = (T_out + CHUNK - 1) / CHUNK;
        dim3 grid(n_chunks, rows);
        spike2calcium_generic<<<grid, THREADS>>>(u, (float*)d_out, K, T_out, in_w);
    }
}

// round 11
// speedup vs baseline: 1.1193x; 1.0373x over previous
#include <cuda_runtime.h>
#include <cuda_bf16.h>
#include <math.h>
#include <stdint.h>

// SpikeToCalciumDoubleExp: out[b,t] = sum_{j=0}^{K-1} kernel[j] * u[b, t+K-1-j]
// kernel[j] = (g1^{j+1} - g2^{j+1})/scale, g = exp(-1/tau), tau1=20, tau2=2, K=121.
//
// Exact per-channel recursion P(j+1) = g*P(j) + (g/scale)*u[j+121]
//                                    - (g^{122}/scale)*u[j].
// Seed decomposition for LPT=17 (121 = 7*17 + 2): each thread publishes, over
// its own 17-sample chunk x[]:
//   M17 (17-tap g1 Horner), M2 (state after 2 taps),
//   G17 (17-tap g2 Horner), G2 (state after 2 taps).
// Thread i's seeds are Horner chains over the tables:
//   U1 = ((((M_i*g1^17 + M_{i+1})*g1^17 + ... + M_{i+6})*g1^2) + M2_{i+7}
//   Q  = cn2 * ((G17_{i+5}*g2^17 + G17_{i+6})*g2^2 + G2_{i+7})
//        (g2 support = last 36 taps; dropped weight ~1.5e-8; g2^122 ~ 0)
// 2 chunks per block, double-buffered cp.async (fire-and-forget both windows
// up front) so chunk 1's HBM traffic overlaps chunk 0's compute+store.
// Small chunks keep smem at ~40KB/block -> 5 blocks/SM (occ ~62% vs 34.6%).
// Stride-17 (odd) per-lane smem access: bank-conflict-free.

#define THREADS 256
#define LPT 17                       // outputs per thread (odd: conflict-free)
#define CHUNK (THREADS * LPT)        // 4352 outputs per chunk
#define WIN (CHUNK + 128)            // input window incl. K-1 lookahead
#define NM (THREADS + 7)             // Horner tables incl. 7 overhang chunks
#define NCPB 2                       // chunks per block (double buffer)

__device__ __forceinline__ void cp_async16(uint32_t saddr, const float* gptr) {
    asm volatile("cp.async.cg.shared.global [%0], [%1], 16;\n"
                 :: "r"(saddr), "l"(gptr));
}
__device__ __forceinline__ void cp_commit() {
    asm volatile("cp.async.commit_group;\n");
}
template<int N> __device__ __forceinline__ void cp_wait() {
    asm volatile("cp.async.wait_group %0;\n" :: "n"(N));
}

// ---------------- pipelined K=121 fast path ----------------
__global__ void __launch_bounds__(THREADS, 5)
spike2calcium_pipe(const float* __restrict__ u, float* __restrict__ out,
                   int T_out, int in_w) {
    extern __shared__ float dynsm[];          // NCPB buffers of WIN floats
    __shared__ float Msm[NM], M2sm[NM], Gsm[NM], G2sm[NM];

    const int tid = threadIdx.x;
    const int b   = blockIdx.y;
    const int c0  = blockIdx.x * NCPB;        // first global chunk index

    // ---- filter constants ----
    const float tau1 = 20.0f, tau2 = 2.0f;
    const float rr = tau1 / tau2, dd = tau1 - tau2;
    const float scale = powf(rr, -tau2 / dd) - powf(rr, -tau1 / dd);
    const float inv_scale = 1.0f / scale;
    const float g1 = expf(-1.0f / tau1);
    const float g2 = expf(-1.0f / tau2);
    const float cn1 = g1 * inv_scale;
    const float cn2 = g2 * inv_scale;
    const float co1 = expf(-122.0f / tau1) * inv_scale;   // g1^122/scale
    const float p17 = expf(-17.0f / tau1);    // g1^17
    const float p2  = expf(-2.0f  / tau1);    // g1^2
    const float q17 = expf(-17.0f / tau2);    // g2^17
    const float q2  = expf(-2.0f  / tau2);    // g2^2

    const float* rowbase = u + (size_t)b * in_w;

    // ---- issue BOTH chunk loads up-front (fire-and-forget) ----
    #pragma unroll
    for (int c = 0; c < NCPB; ++c) {
        const int t0 = (c0 + c) * CHUNK;
        if (t0 < T_out) {
            float* buf = dynsm + c * WIN;
            const int wlen = min(WIN, in_w - t0);
            const float* gp = rowbase + t0;
            if (((uintptr_t)gp & 15u) == 0) {
                const int nv = wlen >> 2;
                uint32_t sb = (uint32_t)__cvta_generic_to_shared(buf);
                for (int v = tid; v < nv; v += THREADS)
                    cp_async16(sb + (v << 4), gp + (v << 2));
                for (int j = (nv << 2) + tid; j < wlen; j += THREADS)
                    buf[j] = gp[j];
            } else {
                for (int j = tid; j < wlen; j += THREADS)
                    buf[j] = gp[j];
            }
        }
        cp_commit();                           // keep group count fixed
    }

    // ---- process chunks ----
    #pragma unroll
    for (int c = 0; c < NCPB; ++c) {
        const int t0 = (c0 + c) * CHUNK;
        if (t0 >= T_out) break;                // uniform across block
        float* sm = dynsm + c * WIN;

        if (c == 0) cp_wait<NCPB - 1>(); else cp_wait<0>();
        __syncthreads();                       // window c resident

        const int base = tid * LPT;
        int nout = T_out - t0 - base;
        nout = min(nout, LPT);

        // phase 2: own-chunk Horners over register array x[]
        float x[LPT];
        float M = 0.0f, G = 0.0f, M2s = 0.0f, G2s = 0.0f;
        #pragma unroll
        for (int r = 0; r < LPT; ++r) {
            x[r] = sm[base + r];
            M = fmaf(M, g1, x[r]);
            G = fmaf(G, g2, x[r]);
            if (r == 1) { M2s = M; G2s = G; }
        }
        Msm[tid]  = M;
        M2sm[tid] = M2s;
        Gsm[tid]  = G;
        G2sm[tid] = G2s;
        if (tid < 7) {                         // overhang chunks 256..262
            float Mo = 0.0f, Go = 0.0f, M2o = 0.0f, G2o = 0.0f;
            const int ob = CHUNK + tid * LPT;
            #pragma unroll
            for (int r = 0; r < LPT; ++r) {
                float v = sm[ob + r];
                Mo = fmaf(Mo, g1, v);
                Go = fmaf(Go, g2, v);
                if (r == 1) { M2o = Mo; G2o = Go; }
            }
            Msm[THREADS + tid]  = Mo;
            M2sm[THREADS + tid] = M2o;
            Gsm[THREADS + tid]  = Go;
            G2sm[THREADS + tid] = G2o;
        }
        __syncthreads();                       // tables ready

        float o0 = 0.0f;
        if (nout > 0) {
            // g1 seed: Horner over 7 chunk-Horners + 2-tap tail
            float U = M;
            #pragma unroll
            for (int k = 1; k <= 6; ++k)
                U = fmaf(U, p17, Msm[tid + k]);
            U = fmaf(U, p2, M2sm[tid + 7]);
            float P = cn1 * U;
            // g2 seed: last 36 taps (2 chunks + 2-tap tail)
            float QU = fmaf(Gsm[tid + 5], q17, Gsm[tid + 6]);
            QU = fmaf(QU, q2, G2sm[tid + 7]);
            float Q = cn2 * QU;
            o0 = P - Q;

            #pragma unroll
            for (int t = 1; t < LPT; ++t) {
                float xn = sm[base + t + 120];
                float xo = x[t - 1];           // register, no LDS
                P = fmaf(g1, P, fmaf(cn1, xn, -co1 * xo));
                Q = fmaf(g2, Q, cn2 * xn);     // g2^122/scale ~ 3e-27: dropped
                x[t - 1] = P - Q;              // o[t] reuses x[t-1]'s slot
            }
        }

        __syncthreads();                       // all reads of window c done
        if (nout > 0) {                        // restage outputs into buffer c
            sm[base] = o0;
            #pragma unroll
            for (int t = 1; t < LPT; ++t)
                if (t < nout) sm[base + t] = x[t - 1];
        }
        __syncthreads();

        const int olen = min(CHUNK, T_out - t0);
        float* orow = out + (size_t)b * T_out + t0;
        const int nov = olen >> 2;
        for (int v = tid; v < nov; v += THREADS)
            *(float4*)(orow + (v << 2)) = *(const float4*)&sm[v << 2];
        for (int j = (nov << 2) + tid; j < olen; j += THREADS)
            orow[j] = sm[j];
        // next chunk uses the other buffer; table WAR fenced by barriers above.
    }
}

// ---------------- generic runtime-K fallback ----------------
#define GLPT 31
#define GCHUNK (THREADS * GLPT)
#define GWIN (GCHUNK + 128)

__global__ void __launch_bounds__(THREADS, 5)
spike2calcium_generic(const float* __restrict__ u, float* __restrict__ out,
                      int K, int T_out, int in_w) {
    __shared__ float sm[GWIN];
    const int tid = threadIdx.x;
    const int b   = blockIdx.y;
    const int t0  = blockIdx.x * GCHUNK;

    const float tau1 = 20.0f, tau2 = 2.0f;
    const float rr = tau1 / tau2, dd = tau1 - tau2;
    const float scale = powf(rr, -tau2 / dd) - powf(rr, -tau1 / dd);
    const float inv_scale = 1.0f / scale;
    const float g1 = expf(-1.0f / tau1);
    const float g2 = expf(-1.0f / tau2);
    const float cn1 = g1 * inv_scale;
    const float cn2 = g2 * inv_scale;

    const float* row = u + (size_t)b * in_w + t0;
    const int wlen = min(GWIN, in_w - t0);
    const int nv = wlen >> 2;
    const float4* row4 = (const float4*)row;
    for (int v = tid; v < nv; v += THREADS)
        *(float4*)&sm[v << 2] = row4[v];
    for (int j = (nv << 2) + tid; j < wlen; j += THREADS)
        sm[j] = row[j];
    __syncthreads();

    const int base = tid * GLPT;
    int nout = T_out - t0 - base;
    nout = min(nout, GLPT);

    float o[GLPT];
    if (nout > 0) {
        float H1 = 0.0f, H2 = 0.0f;
        for (int r = 0; r < K; ++r) {
            float v = sm[base + r];
            H1 = fmaf(H1, g1, v);
            H2 = fmaf(H2, g2, v);
        }
        float P = H1 * cn1;
        float Q = H2 * cn2;
        o[0] = P - Q;
        const float co1 = expf(-(float)(K + 1) / tau1) * inv_scale;
        const float co2 = expf(-(float)(K + 1) / tau2) * inv_scale;
        #pragma unroll 8
        for (int t = 1; t < GLPT; ++t) {
            float xn = sm[base + t + K - 1];
            float xo = sm[base + t - 1];
            P = fmaf(g1, P, fmaf(cn1, xn, -co1 * xo));
            Q = fmaf(g2, Q, fmaf(cn2, xn, -co2 * xo));
            o[t] = P - Q;
        }
    }
    __syncthreads();
    if (nout > 0) {
        #pragma unroll
        for (int t = 0; t < GLPT; ++t)
            if (t < nout) sm[base + t] = o[t];
    }
    __syncthreads();

    const int olen = min(GCHUNK, T_out - t0);
    float* orow = out + (size_t)b * T_out + t0;
    const int nov = olen >> 2;
    for (int v = tid; v < nov; v += THREADS)
        *(float4*)(orow + (v << 2)) = *(const float4*)&sm[v << 2];
    for (int j = (nov << 2) + tid; j < olen; j += THREADS)
        orow[j] = sm[j];
}

extern "C" void kernel_launch(void* const* d_in, const int* in_sizes, int n_in,
                              void* d_out, int out_size) {
    const float* u = (const float*)d_in[0];
    const int K = in_sizes[1];                              // 121
    const int rows  = (in_sizes[0] - out_size) / (K - 1);   // 1024
    const int T_out = out_size / rows;                      // 30000
    const int in_w  = T_out + K - 1;                        // 30120

    if (K == 121) {
        const int n_chunks = (T_out + CHUNK - 1) / CHUNK;   // 7
        const int bx = (n_chunks + NCPB - 1) / NCPB;        // 4
        const int dsmem = NCPB * WIN * (int)sizeof(float);  // 35840 B
        cudaFuncSetAttribute(spike2calcium_pipe,
                             cudaFuncAttributeMaxDynamicSharedMemorySize, dsmem);
        dim3 grid(bx, rows);
        spike2calcium_pipe<<<grid, THREADS, dsmem>>>(u, (float*)d_out, T_out, in_w);
    } else {
        const int n_chunks = (T_out + GCHUNK - 1) / GCHUNK;
        dim3 grid(n_chunks, rows);
        spike2calcium_generic<<<grid, THREADS>>>(u, (float*)d_out, K, T_out, in_w);
    }
}

// round 15
// speedup vs baseline: 1.1725x; 1.0475x over previous
#include <cuda_runtime.h>
#include <cuda_bf16.h>
#include <math.h>
#include <stdint.h>

// SpikeToCalciumDoubleExp: out[b,t] = sum_{j=0}^{K-1} kernel[j] * u[b, t+K-1-j]
// kernel[j] = (g1^{j+1} - g2^{j+1})/scale, g = exp(-1/tau), tau1=20, tau2=2, K=121.
//
// Exact per-channel recursion P(j+1) = g*P(j) + (g/scale)*u[j+121]
//                                    - (g^{122}/scale)*u[j].
// Seed decomposition for LPT=13 (121 = 9*13 + 4): each thread publishes, over
// its own 13-sample chunk x[]:
//   M13 (13-tap g1 Horner), M4 (state after 4 taps),
//   G13 (13-tap g2 Horner), G4 (state after 4 taps).
// Thread i's seeds:
//   U1 = ((M_i*g1^13 + M_{i+1})*g1^13 + ... + M_{i+8})*g1^4 + M4_{i+9}  (exact)
//   Q  = cn2 * ((G13_{i+7}*g2^13 + G13_{i+8})*g2^4 + G4_{i+9})
//        (g2 support = last 30 taps; dropped weight ~3e-7; g2^122 ~ 0)
// 2 chunks per block, double-buffered cp.async (both windows issued up front).
// LPT=13 shrinks per-thread registers so 6 blocks/SM fit (reg-bound at LPT=17).
// Stride-13 (odd) per-lane smem access: bank-conflict-free.

#define THREADS 256
#define LPT 13                       // outputs per thread (odd: conflict-free)
#define CHUNK (THREADS * LPT)        // 3328 outputs per chunk
#define WIN (CHUNK + 128)            // input window incl. K-1 lookahead
#define NM (THREADS + 9)             // Horner tables incl. 9 overhang chunks
#define NCPB 2                       // chunks per block (double buffer)

__device__ __forceinline__ void cp_async16(uint32_t saddr, const float* gptr) {
    asm volatile("cp.async.cg.shared.global [%0], [%1], 16;\n"
                 :: "r"(saddr), "l"(gptr));
}
__device__ __forceinline__ void cp_commit() {
    asm volatile("cp.async.commit_group;\n");
}
template<int N> __device__ __forceinline__ void cp_wait() {
    asm volatile("cp.async.wait_group %0;\n" :: "n"(N));
}

// ---------------- pipelined K=121 fast path ----------------
__global__ void __launch_bounds__(THREADS, 6)
spike2calcium_pipe(const float* __restrict__ u, float* __restrict__ out,
                   int T_out, int in_w) {
    extern __shared__ float dynsm[];          // NCPB buffers of WIN floats
    __shared__ float Msm[NM], M4sm[NM], Gsm[NM], G4sm[NM];

    const int tid = threadIdx.x;
    const int b   = blockIdx.y;
    const int c0  = blockIdx.x * NCPB;        // first global chunk index

    // ---- filter constants ----
    const float tau1 = 20.0f, tau2 = 2.0f;
    const float rr = tau1 / tau2, dd = tau1 - tau2;
    const float scale = powf(rr, -tau2 / dd) - powf(rr, -tau1 / dd);
    const float inv_scale = 1.0f / scale;
    const float g1 = expf(-1.0f / tau1);
    const float g2 = expf(-1.0f / tau2);
    const float cn1 = g1 * inv_scale;
    const float cn2 = g2 * inv_scale;
    const float co1 = expf(-122.0f / tau1) * inv_scale;   // g1^122/scale
    const float p13 = expf(-13.0f / tau1);    // g1^13
    const float p4  = expf(-4.0f  / tau1);    // g1^4
    const float q13 = expf(-13.0f / tau2);    // g2^13
    const float q4  = expf(-4.0f  / tau2);    // g2^4

    const float* rowbase = u + (size_t)b * in_w;

    // ---- issue BOTH chunk loads up-front (fire-and-forget) ----
    #pragma unroll
    for (int c = 0; c < NCPB; ++c) {
        const int t0 = (c0 + c) * CHUNK;
        if (t0 < T_out) {
            float* buf = dynsm + c * WIN;
            const int wlen = min(WIN, in_w - t0);
            const float* gp = rowbase + t0;
            if (((uintptr_t)gp & 15u) == 0) {
                const int nv = wlen >> 2;
                uint32_t sb = (uint32_t)__cvta_generic_to_shared(buf);
                for (int v = tid; v < nv; v += THREADS)
                    cp_async16(sb + (v << 4), gp + (v << 2));
                for (int j = (nv << 2) + tid; j < wlen; j += THREADS)
                    buf[j] = gp[j];
            } else {
                for (int j = tid; j < wlen; j += THREADS)
                    buf[j] = gp[j];
            }
        }
        cp_commit();                           // keep group count fixed
    }

    // ---- process chunks ----
    #pragma unroll
    for (int c = 0; c < NCPB; ++c) {
        const int t0 = (c0 + c) * CHUNK;
        if (t0 >= T_out) break;                // uniform across block
        float* sm = dynsm + c * WIN;

        if (c == 0) cp_wait<NCPB - 1>(); else cp_wait<0>();
        __syncthreads();                       // window c resident

        const int base = tid * LPT;
        int nout = T_out - t0 - base;
        nout = min(nout, LPT);

        // phase 2: own-chunk Horners over register array x[]
        float x[LPT];
        float M = 0.0f, G = 0.0f, M4s = 0.0f, G4s = 0.0f;
        #pragma unroll
        for (int r = 0; r < LPT; ++r) {
            x[r] = sm[base + r];
            M = fmaf(M, g1, x[r]);
            G = fmaf(G, g2, x[r]);
            if (r == 3) { M4s = M; G4s = G; }
        }
        Msm[tid]  = M;
        M4sm[tid] = M4s;
        Gsm[tid]  = G;
        G4sm[tid] = G4s;
        if (tid < 9) {                         // overhang chunks 256..264
            float Mo = 0.0f, Go = 0.0f, M4o = 0.0f, G4o = 0.0f;
            const int ob = CHUNK + tid * LPT;
            #pragma unroll
            for (int r = 0; r < LPT; ++r) {
                float v = sm[ob + r];
                Mo = fmaf(Mo, g1, v);
                Go = fmaf(Go, g2, v);
                if (r == 3) { M4o = Mo; G4o = Go; }
            }
            Msm[THREADS + tid]  = Mo;
            M4sm[THREADS + tid] = M4o;
            Gsm[THREADS + tid]  = Go;
            G4sm[THREADS + tid] = G4o;
        }
        __syncthreads();                       // tables ready

        float o0 = 0.0f;
        if (nout > 0) {
            // g1 seed: Horner over 9 chunk-Horners + 4-tap tail (exact)
            float U = M;
            #pragma unroll
            for (int k = 1; k <= 8; ++k)
                U = fmaf(U, p13, Msm[tid + k]);
            U = fmaf(U, p4, M4sm[tid + 9]);
            float P = cn1 * U;
            // g2 seed: last 30 taps (2 chunks + 4-tap tail)
            float QU = fmaf(Gsm[tid + 7], q13, Gsm[tid + 8]);
            QU = fmaf(QU, q4, G4sm[tid + 9]);
            float Q = cn2 * QU;
            o0 = P - Q;

            #pragma unroll
            for (int t = 1; t < LPT; ++t) {
                float xn = sm[base + t + 120];
                float xo = x[t - 1];           // register, no LDS
                P = fmaf(g1, P, fmaf(cn1, xn, -co1 * xo));
                Q = fmaf(g2, Q, cn2 * xn);     // g2^122/scale ~ 3e-27: dropped
                x[t - 1] = P - Q;              // o[t] reuses x[t-1]'s slot
            }
        }

        __syncthreads();                       // all reads of window c done
        if (nout > 0) {                        // restage outputs into buffer c
            sm[base] = o0;
            #pragma unroll
            for (int t = 1; t < LPT; ++t)
                if (t < nout) sm[base + t] = x[t - 1];
        }
        __syncthreads();

        const int olen = min(CHUNK, T_out - t0);
        float* orow = out + (size_t)b * T_out + t0;
        const int nov = olen >> 2;
        for (int v = tid; v < nov; v += THREADS)
            *(float4*)(orow + (v << 2)) = *(const float4*)&sm[v << 2];
        for (int j = (nov << 2) + tid; j < olen; j += THREADS)
            orow[j] = sm[j];
        // next chunk uses the other buffer; table WAR fenced by barriers above.
    }
}

// ---------------- generic runtime-K fallback ----------------
#define GLPT 31
#define GCHUNK (THREADS * GLPT)
#define GWIN (GCHUNK + 128)

__global__ void __launch_bounds__(THREADS, 5)
spike2calcium_generic(const float* __restrict__ u, float* __restrict__ out,
                      int K, int T_out, int in_w) {
    __shared__ float sm[GWIN];
    const int tid = threadIdx.x;
    const int b   = blockIdx.y;
    const int t0  = blockIdx.x * GCHUNK;

    const float tau1 = 20.0f, tau2 = 2.0f;
    const float rr = tau1 / tau2, dd = tau1 - tau2;
    const float scale = powf(rr, -tau2 / dd) - powf(rr, -tau1 / dd);
    const float inv_scale = 1.0f / scale;
    const float g1 = expf(-1.0f / tau1);
    const float g2 = expf(-1.0f / tau2);
    const float cn1 = g1 * inv_scale;
    const float cn2 = g2 * inv_scale;

    const float* row = u + (size_t)b * in_w + t0;
    const int wlen = min(GWIN, in_w - t0);
    const int nv = wlen >> 2;
    const float4* row4 = (const float4*)row;
    for (int v = tid; v < nv; v += THREADS)
        *(float4*)&sm[v << 2] = row4[v];
    for (int j = (nv << 2) + tid; j < wlen; j += THREADS)
        sm[j] = row[j];
    __syncthreads();

    const int base = tid * GLPT;
    int nout = T_out - t0 - base;
    nout = min(nout, GLPT);

    float o[GLPT];
    if (nout > 0) {
        float H1 = 0.0f, H2 = 0.0f;
        for (int r = 0; r < K; ++r) {
            float v = sm[base + r];
            H1 = fmaf(H1, g1, v);
            H2 = fmaf(H2, g2, v);
        }
        float P = H1 * cn1;
        float Q = H2 * cn2;
        o[0] = P - Q;
        const float co1 = expf(-(float)(K + 1) / tau1) * inv_scale;
        const float co2 = expf(-(float)(K + 1) / tau2) * inv_scale;
        #pragma unroll 8
        for (int t = 1; t < GLPT; ++t) {
            float xn = sm[base + t + K - 1];
            float xo = sm[base + t - 1];
            P = fmaf(g1, P, fmaf(cn1, xn, -co1 * xo));
            Q = fmaf(g2, Q, fmaf(cn2, xn, -co2 * xo));
            o[t] = P - Q;
        }
    }
    __syncthreads();
    if (nout > 0) {
        #pragma unroll
        for (int t = 0; t < GLPT; ++t)
            if (t < nout) sm[base + t] = o[t];
    }
    __syncthreads();

    const int olen = min(GCHUNK, T_out - t0);
    float* orow = out + (size_t)b * T_out + t0;
    const int nov = olen >> 2;
    for (int v = tid; v < nov; v += THREADS)
        *(float4*)(orow + (v << 2)) = *(const float4*)&sm[v << 2];
    for (int j = (nov << 2) + tid; j < olen; j += THREADS)
        orow[j] = sm[j];
}

extern "C" void kernel_launch(void* const* d_in, const int* in_sizes, int n_in,
                              void* d_out, int out_size) {
    const float* u = (const float*)d_in[0];
    const int K = in_sizes[1];                              // 121
    const int rows  = (in_sizes[0] - out_size) / (K - 1);   // 1024
    const int T_out = out_size / rows;                      // 30000
    const int in_w  = T_out + K - 1;                        // 30120

    if (K == 121) {
        const int n_chunks = (T_out + CHUNK - 1) / CHUNK;   // 10
        const int bx = (n_chunks + NCPB - 1) / NCPB;        // 5
        const int dsmem = NCPB * WIN * (int)sizeof(float);  // 27648 B
        cudaFuncSetAttribute(spike2calcium_pipe,
                             cudaFuncAttributeMaxDynamicSharedMemorySize, dsmem);
        dim3 grid(bx, rows);
        spike2calcium_pipe<<<grid, THREADS, dsmem>>>(u, (float*)d_out, T_out, in_w);
    } else {
        const int n_chunks = (T_out + GCHUNK - 1) / GCHUNK;
        dim3 grid(n_chunks, rows);
        spike2calcium_generic<<<grid, THREADS>>>(u, (float*)d_out, K, T_out, in_w);
    }
}